// round 17
// baseline (speedup 1.0000x reference)
#include <cuda_runtime.h>
#include <cstdint>

#define D_DIM 64
#define BT 64
#define NT 64
#define TPB 256
#define XSTRIDE 68
#define ASTRIDE 68

extern __shared__ float smem_dyn[];

// One 4-dim block: 4 b x 4 n per thread, ALL-SCALAR math.
// Scalar FFMA runs at rt=1/SMSP (32 lanes/cyc); packed f32x2 measured rt~10 (trap).
__device__ __forceinline__ void do_dblk(const float* __restrict__ xrow,
                                        const float* __restrict__ arow,
                                        const float* __restrict__ brow,
                                        int dblk,
                                        float (&s)[4][4], float (&p)[4][4])
{
    float xq[4][4];
    #pragma unroll
    for (int bi = 0; bi < 4; bi++) {
        float4 v = *reinterpret_cast<const float4*>(xrow + bi * XSTRIDE + dblk);
        xq[bi][0] = v.x; xq[bi][1] = v.y; xq[bi][2] = v.z; xq[bi][3] = v.w;
    }
    #pragma unroll
    for (int dd = 0; dd < 4; dd++) {
        const int off = (dblk + dd) * ASTRIDE;
        const float4 av = *reinterpret_cast<const float4*>(arow + off);
        const float4 bv = *reinterpret_cast<const float4*>(brow + off);
        const float A[4]  = {av.x, av.y, av.z, av.w};
        const float Bv[4] = {bv.x, bv.y, bv.z, bv.w};
        #pragma unroll
        for (int bi = 0; bi < 4; bi++) {
            const float xs = xq[bi][dd];
            #pragma unroll
            for (int nj = 0; nj < 4; nj++) {
                float z = fmaf(xs, A[nj], Bv[nj]);
                float w = fmaf(z, z, -1.0f);      // z^2 - 1
                s[bi][nj] += w;                   // sum z^2 = sum w + count
                p[bi][nj] *= w;                   // prod (z^2 - 1)
            }
        }
    }
}

__global__ __launch_bounds__(TPB, 3)
void wavelet_kernel(const float* __restrict__ x,
                    const float* __restrict__ centers,
                    const float* __restrict__ scales,
                    float* __restrict__ out, int N)
{
    float* sx = smem_dyn;                   // [BT][XSTRIDE]
    float* sa = sx + BT * XSTRIDE;          // [D][ASTRIDE]  1/s (d-major)
    float* sb = sa + D_DIM * ASTRIDE;       // [D][ASTRIDE]  -c/s

    const int tid = threadIdx.x;
    const int b0 = blockIdx.x * BT;
    const int n0 = blockIdx.y * NT;

    #pragma unroll 2
    for (int i = tid; i < BT * D_DIM; i += TPB) {
        int r = i >> 6, c = i & 63;
        sx[r * XSTRIDE + c] = x[(b0 + r) * D_DIM + c];
    }
    #pragma unroll 4
    for (int i = tid; i < NT * D_DIM; i += TPB) {
        int d = i & 63, n = i >> 6;
        int g = (n0 + n) * D_DIM + d;
        float inv = 1.0f / scales[g];
        sa[d * ASTRIDE + n] = inv;
        sb[d * ASTRIDE + n] = -centers[g] * inv;
    }
    __syncthreads();

    const int ng = tid & 15;           // 4 n's at ng*4
    const int bg = tid >> 4;           // 4 b's at bg*4
    const int rot = (tid >> 5) & 7;    // warp desync (R13)

    const float* xrow = sx + (bg * 4) * XSTRIDE;
    const float* arow = sa + ng * 4;
    const float* brow = sb + ng * 4;

    float s[4][4], p[4][4];
    #pragma unroll
    for (int bi = 0; bi < 4; bi++)
        #pragma unroll
        for (int nj = 0; nj < 4; nj++) { s[bi][nj] = 0.0f; p[bi][nj] = 1.0f; }

    // first half: d = 0..31, warp-rotated block order
    #pragma unroll 2
    for (int q = 0; q < 8; q++)
        do_dblk(xrow, arow, brow, ((q + rot) & 7) * 4, s, p);

    // range-control fold: Gaussian factor for first 32 dims
    #pragma unroll
    for (int bi = 0; bi < 4; bi++)
        #pragma unroll
        for (int nj = 0; nj < 4; nj++) {
            p[bi][nj] *= __expf(-0.5f * (s[bi][nj] + 32.0f));
            s[bi][nj] = 0.0f;
        }

    // second half: d = 32..63
    #pragma unroll 2
    for (int q = 0; q < 8; q++)
        do_dblk(xrow, arow, brow, 32 + ((q + rot) & 7) * 4, s, p);

    // epilogue
    float* orow = out + (long)(b0 + bg * 4) * N + n0 + ng * 4;
    #pragma unroll
    for (int bi = 0; bi < 4; bi++) {
        float h[4];
        #pragma unroll
        for (int nj = 0; nj < 4; nj++)
            h[nj] = p[bi][nj] * __expf(-0.5f * (s[bi][nj] + 32.0f));
        float4 v = {h[0], h[1], h[2], h[3]};
        *reinterpret_cast<float4*>(orow + (long)bi * N) = v;
    }
}

extern "C" void kernel_launch(void* const* d_in, const int* in_sizes, int n_in,
                              void* d_out, int out_size)
{
    const float* x       = (const float*)d_in[0];
    const float* centers = (const float*)d_in[1];
    const float* scales  = (const float*)d_in[2];
    float* out = (float*)d_out;

    const int B = in_sizes[0] / D_DIM;   // 8192
    const int N = in_sizes[1] / D_DIM;   // 512

    const int smem_bytes = (BT * XSTRIDE + 2 * D_DIM * ASTRIDE) * sizeof(float); // 52224
    static bool attr_set = false;
    if (!attr_set) {
        cudaFuncSetAttribute(wavelet_kernel,
                             cudaFuncAttributeMaxDynamicSharedMemorySize, smem_bytes);
        attr_set = true;
    }

    dim3 grid(B / BT, N / NT);           // (128, 8) = 1024 blocks
    wavelet_kernel<<<grid, TPB, smem_bytes>>>(x, centers, scales, out, N);
}